// round 10
// baseline (speedup 1.0000x reference)
#include <cuda_runtime.h>
#include <cuda_fp16.h>
#include <stdint.h>

#define IN_F   4096
#define OUT_F  11008
#define BATCH  16

#define K_TASK   512                    // k per task (per-block k-chunk)
#define NTILES   1376                   // n-tiles of 8 channels

#define BLOCKS   148
#define THREADS  288                    // 8 consumer warps + 1 producer warp
#define RING     16                     // 16 slots; warp w owns {w, w+8}

#define HALF_K   256                    // k per slot (half task)
#define WROW_B   1088                   // 1024 + 64 pad -> conflict-free LDS.128
#define SLOT_B   (8 * WROW_B)           // 8704 B per slot
#define SLOT_TX  8192                   // actual bytes per fill (8 x 1024)
#define XROW_H   520                    // halves per x row (512 + 8 pad)

#define SMEM_MBAR 0                     // slot s: full @ s*16, empty @ s*16+8
#define SMEM_X    256
#define SMEM_W    (SMEM_X + BATCH * XROW_H * 2)   // 256 + 16640 = 16896
#define SMEM_TOT  (SMEM_W + RING * SLOT_B)        // 156,160 B

// g_xh holds x in PERMUTED k-order: within each 16-k block, half2-pair q
// (q = (k/2) & 7) sits at pair position ((q&1)<<2) | (q>>1), so a raw 16B
// weight quad (phys k 4tq..4tq+3) lines up with MMA B slots {2tq,2tq+1,2tq+8,2tq+9}.
__device__ __half g_xh[BATCH * IN_F];

// ---------------- mbarrier helpers ----------------
#define MB_INIT(addr, cnt) \
    asm volatile("mbarrier.init.shared.b64 [%0], %1;" :: "r"(addr), "r"(cnt) : "memory")
#define MB_EXPECT_TX(addr, bytes) \
    asm volatile("mbarrier.arrive.expect_tx.shared.b64 _, [%0], %1;" :: "r"(addr), "r"(bytes) : "memory")
#define MB_ARRIVE(addr) \
    asm volatile("mbarrier.arrive.shared.b64 _, [%0];" :: "r"(addr) : "memory")
#define MB_WAIT(addr, parity) do {                                            \
    unsigned _done;                                                           \
    asm volatile("{\n\t.reg .pred p;\n\t"                                     \
        "mbarrier.try_wait.parity.acquire.cta.shared::cta.b64 p, [%1], %2;\n\t" \
        "selp.b32 %0, 1, 0, p;\n\t}"                                          \
        : "=r"(_done) : "r"(addr), "r"(parity) : "memory");                   \
    while (!_done) {                                                          \
        asm volatile("{\n\t.reg .pred p;\n\t"                                 \
            "mbarrier.try_wait.parity.acquire.cta.shared::cta.b64 p, [%1], %2, 0x989680;\n\t" \
            "selp.b32 %0, 1, 0, p;\n\t}"                                      \
            : "=r"(_done) : "r"(addr), "r"(parity) : "memory");               \
    }                                                                         \
} while (0)

#define BULK_CP(dst, src, mbar) \
    asm volatile("cp.async.bulk.shared::cta.global.mbarrier::complete_tx::bytes " \
                 "[%0], [%1], %2, [%3];" \
                 :: "r"(dst), "l"(src), "n"(1024), "r"(mbar) : "memory")

// ---------------------------------------------------------------------------
// Prologue: x fp32 -> fp16 (permuted), out = bias.
// ---------------------------------------------------------------------------
__global__ void prologue_kernel(const float* __restrict__ x,
                                const float* __restrict__ bias,
                                float* __restrict__ out) {
    const int i      = blockIdx.x * blockDim.x + threadIdx.x;
    const int stride = gridDim.x * blockDim.x;

    __half2* dst = (__half2*)g_xh;
    const int nh2 = BATCH * IN_F / 2;
    for (int j = i; j < nh2; j += stride) {
        float2 v = ((const float2*)x)[j];
        int q   = j & 7;
        int pos = (j & ~7) | ((q & 1) << 2) | (q >> 1);
        dst[pos] = __floats2half2_rn(v.x, v.y);
    }

    const float4* b4 = (const float4*)bias;
    const int total4 = BATCH * OUT_F / 4;
    const int row4   = OUT_F / 4;
    for (int j = i; j < total4; j += stride) {
        ((float4*)out)[j] = __ldg(b4 + (j % row4));
    }
}

// ---------------------------------------------------------------------------
// GEMM: per-block k-chunk; producer warp streams task halves (8 KB) into a
// 16-slot ring; consumer warp w owns slots {w, w+8} -> per-warp depth-2
// pipeline (compute h0 while h1 lands, next h0 refills under h1 compute).
// ---------------------------------------------------------------------------
extern __shared__ char smem[];

__global__ void __launch_bounds__(THREADS, 1)
gemm_kernel(const int* __restrict__ W,
            const float* __restrict__ scale,
            float* __restrict__ out) {
    const int tid  = threadIdx.x;
    const int lane = tid & 31;
    const int wid  = tid >> 5;

    const int kc  = blockIdx.x & 7;
    const int bi  = blockIdx.x >> 3;
    const int Bkc = (kc < 4) ? 19 : 18;             // blocks sharing this kc
    const int T   = (NTILES - bi + Bkc - 1) / Bkc;  // tasks for this block

    const unsigned sb = (unsigned)__cvta_generic_to_shared(smem);

    // ---- init mbarriers ----
    if (tid == 0) {
        #pragma unroll
        for (int s = 0; s < RING; s++) {
            MB_INIT(sb + SMEM_MBAR + s * 16,     1u);   // full
            MB_INIT(sb + SMEM_MBAR + s * 16 + 8, 1u);   // empty
        }
        asm volatile("fence.proxy.async.shared::cta;" ::: "memory");
    }

    // ---- stage this block's x k-slice (16 rows x 512 halves, permuted) ----
    {
        const uint4* src = (const uint4*)g_xh;
        for (int i = tid; i < BATCH * (K_TASK / 8); i += THREADS) {
            int r = i >> 6, c = i & 63;
            uint4 v = src[(r * IN_F + kc * K_TASK) / 8 + c];
            *(uint4*)(smem + SMEM_X + (r * XROW_H + c * 8) * 2) = v;
        }
    }
    __syncthreads();

    if (wid == 8) {
        // ================= producer =================
        if (lane == 0) {
            for (int j = 0; j < T; j++) {
                const int sw    = j & 7;
                const int round = j >> 3;
                const unsigned pw = (unsigned)((round & 1) ^ 1);
                const int n = bi + j * Bkc;
                const char* src = (const char*)(W + (size_t)n * 8 * IN_F + kc * K_TASK);

                #pragma unroll
                for (int h = 0; h < 2; h++) {
                    const int s = sw + h * 8;
                    MB_WAIT(sb + SMEM_MBAR + s * 16 + 8, pw);
                    MB_EXPECT_TX(sb + SMEM_MBAR + s * 16, (unsigned)SLOT_TX);
                    const unsigned dst = sb + SMEM_W + s * SLOT_B;
                    const char* hsrc = src + h * (HALF_K * 4);
                    #pragma unroll
                    for (int r = 0; r < 8; r++) {
                        BULK_CP(dst + r * WROW_B, hsrc + (size_t)r * (IN_F * 4),
                                sb + SMEM_MBAR + s * 16);
                    }
                }
            }
        }
        return;
    }

    // ================= consumers (warps 0..7) =================
    const int ng = lane >> 2;      // weight row within n-tile
    const int tq = lane & 3;       // k-quad

    const unsigned a_off = sb + SMEM_X +
        (unsigned)((lane & 15) * (XROW_H * 2) + ((lane >> 4) & 1) * 16);
    const char* wbase = smem + SMEM_W + ng * WROW_B + tq * 16;
    const unsigned mb = sb + SMEM_MBAR;

    int r = 0;
    for (int j = wid; j < T; j += 8, r++) {
        const int n = bi + j * Bkc;
        const unsigned par = (unsigned)(r & 1);
        float c0 = 0.f, c1 = 0.f, c2 = 0.f, c3 = 0.f;

        #pragma unroll
        for (int h = 0; h < 2; h++) {
            const int s = wid + h * 8;
            MB_WAIT(mb + s * 16, par);
            const char* wslot = wbase + s * SLOT_B;

            #pragma unroll
            for (int i = 0; i < 16; i++) {
                const int t = h * 16 + i;
                unsigned a0, a1, a2, a3;
                asm volatile(
                    "ldmatrix.sync.aligned.m8n8.x4.shared.b16 {%0,%1,%2,%3}, [%4];"
                    : "=r"(a0), "=r"(a1), "=r"(a2), "=r"(a3)
                    : "r"(a_off + (unsigned)(t * 32)));

                int4 w = *(const int4*)(wslot + i * 64);
                __half2 hb0 = __halves2half2(__int2half_rn(w.x), __int2half_rn(w.y));
                __half2 hb1 = __halves2half2(__int2half_rn(w.z), __int2half_rn(w.w));
                unsigned b0 = *reinterpret_cast<unsigned*>(&hb0);
                unsigned b1 = *reinterpret_cast<unsigned*>(&hb1);

                asm volatile(
                    "mma.sync.aligned.m16n8k16.row.col.f32.f16.f16.f32 "
                    "{%0,%1,%2,%3}, {%4,%5,%6,%7}, {%8,%9}, {%0,%1,%2,%3};"
                    : "+f"(c0), "+f"(c1), "+f"(c2), "+f"(c3)
                    : "r"(a0), "r"(a1), "r"(a2), "r"(a3), "r"(b0), "r"(b1));
            }

            __syncwarp();
            if (lane == 0) MB_ARRIVE(mb + s * 16 + 8);
        }

        // ---- epilogue: scale, accumulate (out already holds bias) ----
        const int o0 = n * 8 + tq * 2;
        const float s0  = __ldg(scale + o0);
        const float s1f = __ldg(scale + o0 + 1);
        atomicAdd(&out[(size_t)ng * OUT_F + o0],           c0 * s0);
        atomicAdd(&out[(size_t)ng * OUT_F + o0 + 1],       c1 * s1f);
        atomicAdd(&out[(size_t)(ng + 8) * OUT_F + o0],     c2 * s0);
        atomicAdd(&out[(size_t)(ng + 8) * OUT_F + o0 + 1], c3 * s1f);
    }
}

// ---------------------------------------------------------------------------
extern "C" void kernel_launch(void* const* d_in, const int* in_sizes, int n_in,
                              void* d_out, int out_size) {
    const float* x     = (const float*)d_in[0];
    const int*   w     = (const int*)  d_in[1];
    const float* scale = (const float*)d_in[2];
    const float* bias  = (const float*)d_in[3];
    float*       out   = (float*)d_out;

    cudaFuncSetAttribute(gemm_kernel,
                         cudaFuncAttributeMaxDynamicSharedMemorySize, SMEM_TOT);

    prologue_kernel<<<344, 256>>>(x, bias, out);
    gemm_kernel<<<BLOCKS, THREADS, SMEM_TOT>>>(w, scale, out);
}

// round 12
// speedup vs baseline: 2.1647x; 2.1647x over previous
#include <cuda_runtime.h>
#include <cuda_fp16.h>
#include <stdint.h>

#define IN_F   4096
#define OUT_F  11008
#define BATCH  16

#define K_TASK   512                    // k per task (per-block k-chunk)
#define NTILES   1376                   // n-tiles of 8 channels

#define BLOCKS   148
#define THREADS  224                    // 6 consumer warps + 1 producer warp
#define NCONS    6                      // consumer warps
#define RING     12                     // warp w owns slots {w, w+6}

#define WROW_B   2112                   // 2048 + 64 pad -> conflict-free LDS.128
#define SLOT_B   (8 * WROW_B)           // 16,896 B per slot
#define SLOT_TX  16384                  // actual bytes per fill (8 x 2048)
#define XROW_H   520                    // halves per x row (512 + 8 pad)

#define SMEM_MBAR 0                     // slot s: full @ s*16, empty @ s*16+8
#define SMEM_X    256
#define SMEM_W    (SMEM_X + BATCH * XROW_H * 2)   // 256 + 16640 = 16896
#define SMEM_TOT  (SMEM_W + RING * SLOT_B)        // 219,648 B (< 227KB opt-in)

// g_xh holds x in PERMUTED k-order: within each 16-k block, half2-pair q
// (q = (k/2) & 7) sits at pair position ((q&1)<<2) | (q>>1), so a raw 16B
// weight quad (phys k 4tq..4tq+3) lines up with MMA B slots {2tq,2tq+1,2tq+8,2tq+9}.
__device__ __half g_xh[BATCH * IN_F];

// ---------------- mbarrier helpers ----------------
#define MB_INIT(addr, cnt) \
    asm volatile("mbarrier.init.shared.b64 [%0], %1;" :: "r"(addr), "r"(cnt) : "memory")
#define MB_EXPECT_TX(addr, bytes) \
    asm volatile("mbarrier.arrive.expect_tx.shared.b64 _, [%0], %1;" :: "r"(addr), "r"(bytes) : "memory")
#define MB_ARRIVE(addr) \
    asm volatile("mbarrier.arrive.shared.b64 _, [%0];" :: "r"(addr) : "memory")
#define MB_WAIT(addr, parity) do {                                            \
    unsigned _done;                                                           \
    asm volatile("{\n\t.reg .pred p;\n\t"                                     \
        "mbarrier.try_wait.parity.acquire.cta.shared::cta.b64 p, [%1], %2;\n\t" \
        "selp.b32 %0, 1, 0, p;\n\t}"                                          \
        : "=r"(_done) : "r"(addr), "r"(parity) : "memory");                   \
    while (!_done) {                                                          \
        asm volatile("{\n\t.reg .pred p;\n\t"                                 \
            "mbarrier.try_wait.parity.acquire.cta.shared::cta.b64 p, [%1], %2, 0x989680;\n\t" \
            "selp.b32 %0, 1, 0, p;\n\t}"                                      \
            : "=r"(_done) : "r"(addr), "r"(parity) : "memory");               \
    }                                                                         \
} while (0)

#define BULK_CP(dst, src, mbar) \
    asm volatile("cp.async.bulk.shared::cta.global.mbarrier::complete_tx::bytes " \
                 "[%0], [%1], %2, [%3];" \
                 :: "r"(dst), "l"(src), "n"(2048), "r"(mbar) : "memory")

// ---------------------------------------------------------------------------
// Prologue: x fp32 -> fp16 (permuted), out = bias.
// ---------------------------------------------------------------------------
__global__ void prologue_kernel(const float* __restrict__ x,
                                const float* __restrict__ bias,
                                float* __restrict__ out) {
    const int i      = blockIdx.x * blockDim.x + threadIdx.x;
    const int stride = gridDim.x * blockDim.x;

    __half2* dst = (__half2*)g_xh;
    const int nh2 = BATCH * IN_F / 2;
    for (int j = i; j < nh2; j += stride) {
        float2 v = ((const float2*)x)[j];
        int q   = j & 7;
        int pos = (j & ~7) | ((q & 1) << 2) | (q >> 1);
        dst[pos] = __floats2half2_rn(v.x, v.y);
    }

    const float4* b4 = (const float4*)bias;
    const int total4 = BATCH * OUT_F / 4;
    const int row4   = OUT_F / 4;
    for (int j = i; j < total4; j += stride) {
        ((float4*)out)[j] = __ldg(b4 + (j % row4));
    }
}

// ---------------------------------------------------------------------------
// GEMM: per-block k-chunk; producer streams 16KB weight tasks round-robin
// into a 12-slot ring; consumer warp w EXCLUSIVELY owns slots {w, w+6}
// (task j -> warp j%6, slot j%12) -> per-warp depth-2 pipeline with R8's
// proven per-slot single-owner protocol.
// ---------------------------------------------------------------------------
extern __shared__ char smem[];

__global__ void __launch_bounds__(THREADS, 1)
gemm_kernel(const int* __restrict__ W,
            const float* __restrict__ scale,
            float* __restrict__ out) {
    const int tid  = threadIdx.x;
    const int lane = tid & 31;
    const int wid  = tid >> 5;

    const int kc  = blockIdx.x & 7;
    const int bi  = blockIdx.x >> 3;
    const int Bkc = (kc < 4) ? 19 : 18;             // blocks sharing this kc
    const int T   = (NTILES - bi + Bkc - 1) / Bkc;  // tasks for this block

    const unsigned sb = (unsigned)__cvta_generic_to_shared(smem);

    // ---- init mbarriers ----
    if (tid == 0) {
        #pragma unroll
        for (int s = 0; s < RING; s++) {
            MB_INIT(sb + SMEM_MBAR + s * 16,     1u);   // full
            MB_INIT(sb + SMEM_MBAR + s * 16 + 8, 1u);   // empty
        }
        asm volatile("fence.proxy.async.shared::cta;" ::: "memory");
    }

    // ---- stage this block's x k-slice (16 rows x 512 halves, permuted) ----
    {
        const uint4* src = (const uint4*)g_xh;
        for (int i = tid; i < BATCH * (K_TASK / 8); i += THREADS) {
            int r = i >> 6, c = i & 63;
            uint4 v = src[(r * IN_F + kc * K_TASK) / 8 + c];
            *(uint4*)(smem + SMEM_X + (r * XROW_H + c * 8) * 2) = v;
        }
    }
    __syncthreads();

    if (wid == NCONS) {
        // ================= producer =================
        if (lane == 0) {
            for (int j = 0; j < T; j++) {
                const int slot = j % RING;
                const int lap  = j / RING;
                MB_WAIT(sb + SMEM_MBAR + slot * 16 + 8, (unsigned)((lap & 1) ^ 1));
                MB_EXPECT_TX(sb + SMEM_MBAR + slot * 16, (unsigned)SLOT_TX);

                const int n = bi + j * Bkc;
                const char* src = (const char*)(W + (size_t)n * 8 * IN_F + kc * K_TASK);
                const unsigned dst = sb + SMEM_W + slot * SLOT_B;
                #pragma unroll
                for (int r = 0; r < 8; r++) {
                    BULK_CP(dst + r * WROW_B, src + (size_t)r * (IN_F * 4),
                            sb + SMEM_MBAR + slot * 16);
                }
            }
        }
        return;
    }

    // ================= consumers (warps 0..5) =================
    const int ng = lane >> 2;      // weight row within n-tile
    const int tq = lane & 3;       // k-quad

    const unsigned a_off = sb + SMEM_X +
        (unsigned)((lane & 15) * (XROW_H * 2) + ((lane >> 4) & 1) * 16);
    const char* wbase = smem + SMEM_W + ng * WROW_B + tq * 16;
    const unsigned mb = sb + SMEM_MBAR;

    // warp w: r-th task is j = w + 6r, in slot w + 6*(r&1), fill #(r>>1)
    int r = 0;
    for (int j = wid; j < T; j += NCONS, r++) {
        const int      slot = wid + NCONS * (r & 1);
        const unsigned par  = (unsigned)((r >> 1) & 1);
        MB_WAIT(mb + slot * 16, par);

        const int n = bi + j * Bkc;
        const char* wslot = wbase + slot * SLOT_B;
        float c0 = 0.f, c1 = 0.f, c2 = 0.f, c3 = 0.f;

        #pragma unroll 1
        for (int g = 0; g < 4; g++) {            // 4 groups of 8 k16-tiles
            #pragma unroll
            for (int i = 0; i < 8; i++) {
                const int t = g * 8 + i;
                unsigned a0, a1, a2, a3;
                asm volatile(
                    "ldmatrix.sync.aligned.m8n8.x4.shared.b16 {%0,%1,%2,%3}, [%4];"
                    : "=r"(a0), "=r"(a1), "=r"(a2), "=r"(a3)
                    : "r"(a_off + (unsigned)(t * 32)));

                int4 w = *(const int4*)(wslot + t * 64);
                __half2 hb0 = __halves2half2(__int2half_rn(w.x), __int2half_rn(w.y));
                __half2 hb1 = __halves2half2(__int2half_rn(w.z), __int2half_rn(w.w));
                unsigned b0 = *reinterpret_cast<unsigned*>(&hb0);
                unsigned b1 = *reinterpret_cast<unsigned*>(&hb1);

                asm volatile(
                    "mma.sync.aligned.m16n8k16.row.col.f32.f16.f16.f32 "
                    "{%0,%1,%2,%3}, {%4,%5,%6,%7}, {%8,%9}, {%0,%1,%2,%3};"
                    : "+f"(c0), "+f"(c1), "+f"(c2), "+f"(c3)
                    : "r"(a0), "r"(a1), "r"(a2), "r"(a3), "r"(b0), "r"(b1));
            }
        }

        __syncwarp();
        if (lane == 0) MB_ARRIVE(mb + slot * 16 + 8);

        // ---- epilogue: scale, accumulate (out already holds bias) ----
        const int o0 = n * 8 + tq * 2;
        const float s0  = __ldg(scale + o0);
        const float s1f = __ldg(scale + o0 + 1);
        atomicAdd(&out[(size_t)ng * OUT_F + o0],           c0 * s0);
        atomicAdd(&out[(size_t)ng * OUT_F + o0 + 1],       c1 * s1f);
        atomicAdd(&out[(size_t)(ng + 8) * OUT_F + o0],     c2 * s0);
        atomicAdd(&out[(size_t)(ng + 8) * OUT_F + o0 + 1], c3 * s1f);
    }
}

// ---------------------------------------------------------------------------
extern "C" void kernel_launch(void* const* d_in, const int* in_sizes, int n_in,
                              void* d_out, int out_size) {
    const float* x     = (const float*)d_in[0];
    const int*   w     = (const int*)  d_in[1];
    const float* scale = (const float*)d_in[2];
    const float* bias  = (const float*)d_in[3];
    float*       out   = (float*)d_out;

    cudaFuncSetAttribute(gemm_kernel,
                         cudaFuncAttributeMaxDynamicSharedMemorySize, SMEM_TOT);

    prologue_kernel<<<344, 256>>>(x, bias, out);
    gemm_kernel<<<BLOCKS, THREADS, SMEM_TOT>>>(w, scale, out);
}